// round 3
// baseline (speedup 1.0000x reference)
#include <cuda_runtime.h>
#include <cstddef>

// FusionAdjacency: Af = rownorm( sigmoid(g)*scatter(s) + (1-sigmoid(g))*scatter(t) )
// Dense output [N,N] fp32, but only ~2E of 64M cells are nonzero.
// Strategy: memset output, compute row sums from edge lists, scatter normalized
// per-edge contributions with atomicAdd (duplicates coalesce correctly since
// normalization is linear).

#define NN 8192

// Scratch (no device allocation allowed): row sums -> reciprocals, 32 KB.
__device__ float g_row_inv[NN];

__global__ void zero_rowsum_kernel() {
    int i = blockIdx.x * blockDim.x + threadIdx.x;
    if (i < NN) g_row_inv[i] = 0.0f;
}

__global__ void accum_rowsum_kernel(const int* __restrict__ rows_s,
                                    const float* __restrict__ vals_s, int Es,
                                    const int* __restrict__ rows_t,
                                    const float* __restrict__ vals_t, int Et,
                                    const float* __restrict__ gamma) {
    const float g = gamma[0];
    const float alpha = 1.0f / (1.0f + expf(-g));
    const float beta = 1.0f - alpha;
    const int tid = blockIdx.x * blockDim.x + threadIdx.x;
    const int stride = gridDim.x * blockDim.x;
    for (int e = tid; e < Es; e += stride) {
        atomicAdd(&g_row_inv[rows_s[e]], alpha * vals_s[e]);
    }
    for (int e = tid; e < Et; e += stride) {
        atomicAdd(&g_row_inv[rows_t[e]], beta * vals_t[e]);
    }
}

__global__ void finalize_rowsum_kernel() {
    int i = blockIdx.x * blockDim.x + threadIdx.x;
    if (i < NN) {
        float s = g_row_inv[i];
        g_row_inv[i] = (s == 0.0f) ? 1.0f : (1.0f / s);
    }
}

__global__ void scatter_kernel(const int* __restrict__ rows_s,
                               const int* __restrict__ cols_s,
                               const float* __restrict__ vals_s, int Es,
                               const int* __restrict__ rows_t,
                               const int* __restrict__ cols_t,
                               const float* __restrict__ vals_t, int Et,
                               const float* __restrict__ gamma,
                               float* __restrict__ out) {
    const float g = gamma[0];
    const float alpha = 1.0f / (1.0f + expf(-g));
    const float beta = 1.0f - alpha;
    const int tid = blockIdx.x * blockDim.x + threadIdx.x;
    const int stride = gridDim.x * blockDim.x;
    for (int e = tid; e < Es; e += stride) {
        int r = rows_s[e];
        int c = cols_s[e];
        float contrib = alpha * vals_s[e] * g_row_inv[r];
        atomicAdd(&out[(size_t)r * NN + c], contrib);
    }
    for (int e = tid; e < Et; e += stride) {
        int r = rows_t[e];
        int c = cols_t[e];
        float contrib = beta * vals_t[e] * g_row_inv[r];
        atomicAdd(&out[(size_t)r * NN + c], contrib);
    }
}

extern "C" void kernel_launch(void* const* d_in, const int* in_sizes, int n_in,
                              void* d_out, int out_size) {
    // metadata order: rows_s, cols_s, vals_s, rows_t, cols_t, vals_t, gamma
    const int*   rows_s = (const int*)d_in[0];
    const int*   cols_s = (const int*)d_in[1];
    const float* vals_s = (const float*)d_in[2];
    const int*   rows_t = (const int*)d_in[3];
    const int*   cols_t = (const int*)d_in[4];
    const float* vals_t = (const float*)d_in[5];
    const float* gamma  = (const float*)d_in[6];
    float* out = (float*)d_out;

    const int Es = in_sizes[0];
    const int Et = in_sizes[3];

    // 1) zero the 256 MB dense output (harness poisons it to 0xAA)
    cudaMemsetAsync(d_out, 0, (size_t)out_size * sizeof(float), 0);

    // 2) zero row-sum scratch
    zero_rowsum_kernel<<<(NN + 255) / 256, 256>>>();

    // 3) accumulate blended row sums from both edge lists
    {
        int threads = 256;
        int blocks = 1184;  // ~8 waves of edges per thread over 2*262144 edges... grid-stride anyway
        accum_rowsum_kernel<<<blocks, threads>>>(rows_s, vals_s, Es,
                                                 rows_t, vals_t, Et, gamma);
    }

    // 4) finalize reciprocals with zero guard
    finalize_rowsum_kernel<<<(NN + 255) / 256, 256>>>();

    // 5) scatter normalized contributions into dense output
    {
        int threads = 256;
        int blocks = (Es + threads - 1) / threads;  // one edge per thread for list s; grid-stride covers t
        if (blocks > 4096) blocks = 4096;
        scatter_kernel<<<blocks, threads>>>(rows_s, cols_s, vals_s, Es,
                                            rows_t, cols_t, vals_t, Et,
                                            gamma, out);
    }
}